// round 10
// baseline (speedup 1.0000x reference)
#include <cuda_runtime.h>
#include <math.h>

#define N_NODES 100000
#define N_EDGES 1600000
#define D_FEAT  64
#define EPS     1e-7f
#define FULL    0xffffffffu

// Scratch
__device__ float g_inv[N_NODES];          // 1 / ||x_i||
__device__ int   g_col[N_EDGES];          // edge_col as int32
__device__ int   g_row[N_EDGES];          // edge_row as int32
__device__ float g_w[N_EDGES];            // per-edge softmax numerator
__device__ int   g_rowptr[N_NODES + 1];

// ---------------------------------------------------------------------------
__device__ __forceinline__ int detect_is64(const unsigned int* ec_raw)
{
    unsigned acc = 0;
    #pragma unroll
    for (int i = 1; i < 16; i += 2) acc |= ec_raw[i];
    return acc == 0u;
}

__device__ __forceinline__ int get_idx(const void* p, int e, int is64)
{
    if (is64) return (int)((const long long*)p)[e];
    return ((const int*)p)[e];
}

// ---------------------------------------------------------------------------
// Prep kernel: four jobs via block-range split.
// ---------------------------------------------------------------------------
#define B_NORM 6250     // N_NODES*16 / 256
#define B_COL  6250     // N_EDGES / 256 (edge_col convert)
#define B_ROWC 6250     // N_EDGES / 256 (edge_row convert)
#define B_PTR  391      // ceil((N_NODES+1)/256)

__global__ void __launch_bounds__(256)
prep_kernel(const float4* __restrict__ x4,
            const void* __restrict__ er,
            const void* __restrict__ ec)
{
    int b = blockIdx.x;
    if (b < B_NORM) {
        int t    = b * 256 + threadIdx.x;
        int node = t >> 4;
        int sub  = t & 15;
        if (node >= N_NODES) return;
        float4 a = x4[node * 16 + sub];
        float s = a.x * a.x + a.y * a.y + a.z * a.z + a.w * a.w;
        #pragma unroll
        for (int o = 8; o; o >>= 1) s += __shfl_xor_sync(FULL, s, o);
        if (sub == 0) g_inv[node] = rsqrtf(s);
    } else if (b < B_NORM + B_COL) {
        int e = (b - B_NORM) * 256 + threadIdx.x;
        if (e >= N_EDGES) return;
        int is64 = detect_is64((const unsigned int*)ec);
        g_col[e] = get_idx(ec, e, is64);
    } else if (b < B_NORM + B_COL + B_ROWC) {
        int e = (b - B_NORM - B_COL) * 256 + threadIdx.x;
        if (e >= N_EDGES) return;
        int is64 = detect_is64((const unsigned int*)ec);
        g_row[e] = get_idx(er, e, is64);
    } else {
        int i = (b - B_NORM - B_COL - B_ROWC) * 256 + threadIdx.x;
        if (i > N_NODES) return;
        int is64 = detect_is64((const unsigned int*)ec);
        int lo = 0, hi = N_EDGES;
        while (lo < hi) {
            int mid = (lo + hi) >> 1;
            if (get_idx(er, mid, is64) < i) lo = mid + 1; else hi = mid;
        }
        g_rowptr[i] = lo;
    }
}

// ---------------------------------------------------------------------------
// Phase A: per-edge weights, edge-parallel (warp = 32 flat edges).
// Lane = (group g 0..3) x (feature f 0..7); 4 edges per iteration. Indices
// and inv-norm products prefetched cooperatively, broadcast via shuffle.
// w = exp(beta*(cos-1)): shift-invariant softmax numerator, arg <= 0.
// edge_row is sorted, so x[r] gathers hit the same L1 lines repeatedly.
// ---------------------------------------------------------------------------
__global__ void __launch_bounds__(256)
simw_kernel(const float4* __restrict__ x4, const float* __restrict__ beta)
{
    int warp = (blockIdx.x * blockDim.x + threadIdx.x) >> 5;
    int base = warp * 32;
    if (base >= N_EDGES) return;
    int lane = threadIdx.x & 31;
    int g = lane >> 3;
    int f = lane & 7;

    int cnt = N_EDGES - base; if (cnt > 32) cnt = 32;

    int   myc  = (lane < cnt) ? g_col[base + lane] : 0;
    int   myr  = (lane < cnt) ? g_row[base + lane] : 0;
    float myi2 = g_inv[myc] * g_inv[myr];
    float bv   = beta[0];

    int iters = (cnt + 3) >> 2;
    #pragma unroll 2
    for (int it = 0; it < iters; ++it) {
        int   src  = it * 4 + g;
        int   c    = __shfl_sync(FULL, myc,  src);
        int   r    = __shfl_sync(FULL, myr,  src);
        float inv2 = __shfl_sync(FULL, myi2, src);

        float4 a0 = x4[r * 16 + f];
        float4 a1 = x4[r * 16 + 8 + f];
        float4 b0 = x4[c * 16 + f];
        float4 b1 = x4[c * 16 + 8 + f];

        float d = a0.x * b0.x + a0.y * b0.y + a0.z * b0.z + a0.w * b0.w
                + a1.x * b1.x + a1.y * b1.y + a1.z * b1.z + a1.w * b1.w;
        d += __shfl_xor_sync(FULL, d, 1);
        d += __shfl_xor_sync(FULL, d, 2);
        d += __shfl_xor_sync(FULL, d, 4);

        float w = __expf(fmaf(bv * inv2, d, -bv));
        if (f == 0 && src < cnt) g_w[base + src] = w;
    }
}

// ---------------------------------------------------------------------------
// Phase B: dot-free weighted SPMM. ONE WARP PER ROW, 4 edges x 8 lanes.
// Loop body: two sequential broadcast loads (w, col) + one gathered row +
// 8 FMA. No shuffles until the epilogue; low registers -> high occupancy.
// ---------------------------------------------------------------------------
__global__ void __launch_bounds__(256)
spmm_kernel(const float4* __restrict__ x4, float4* __restrict__ out4)
{
    int row = (blockIdx.x * blockDim.x + threadIdx.x) >> 5;
    if (row >= N_NODES) return;
    int lane = threadIdx.x & 31;
    int g = lane >> 3;
    int f = lane & 7;

    int s = g_rowptr[row];
    int n = g_rowptr[row + 1] - s;

    float4 acc0 = make_float4(0.f, 0.f, 0.f, 0.f);
    float4 acc1 = make_float4(0.f, 0.f, 0.f, 0.f);
    float  wsum = 0.f;

    const int*   __restrict__ col = g_col;
    const float* __restrict__ wp  = g_w;

    int nIter = (n + 3) >> 2;
    #pragma unroll 4
    for (int it = 0; it < nIter; ++it) {
        int  e     = (it << 2) + g;
        bool valid = e < n;
        int  idx   = valid ? s + e : s;

        float w = wp[idx];                // broadcast, sequential
        int   c = col[idx];               // broadcast, sequential
        w = valid ? w : 0.f;

        float4 b0 = x4[c * 16 + f];
        float4 b1 = x4[c * 16 + 8 + f];

        wsum  += w;
        acc0.x = fmaf(w, b0.x, acc0.x);
        acc0.y = fmaf(w, b0.y, acc0.y);
        acc0.z = fmaf(w, b0.z, acc0.z);
        acc0.w = fmaf(w, b0.w, acc0.w);
        acc1.x = fmaf(w, b1.x, acc1.x);
        acc1.y = fmaf(w, b1.y, acc1.y);
        acc1.z = fmaf(w, b1.z, acc1.z);
        acc1.w = fmaf(w, b1.w, acc1.w);
    }

    // combine the 4 edge-groups (wsum is identical across f within a group)
    #pragma unroll
    for (int o = 8; o <= 16; o <<= 1) {
        acc0.x += __shfl_xor_sync(FULL, acc0.x, o);
        acc0.y += __shfl_xor_sync(FULL, acc0.y, o);
        acc0.z += __shfl_xor_sync(FULL, acc0.z, o);
        acc0.w += __shfl_xor_sync(FULL, acc0.w, o);
        acc1.x += __shfl_xor_sync(FULL, acc1.x, o);
        acc1.y += __shfl_xor_sync(FULL, acc1.y, o);
        acc1.z += __shfl_xor_sync(FULL, acc1.z, o);
        acc1.w += __shfl_xor_sync(FULL, acc1.w, o);
        wsum   += __shfl_xor_sync(FULL, wsum,   o);
    }

    if (g == 0) {
        float invw = (n > 0) ? (1.f / wsum) : 0.f;
        out4[row * 16 + f]     = make_float4(acc0.x * invw, acc0.y * invw,
                                             acc0.z * invw, acc0.w * invw);
        out4[row * 16 + 8 + f] = make_float4(acc1.x * invw, acc1.y * invw,
                                             acc1.z * invw, acc1.w * invw);
    }
}

// ---------------------------------------------------------------------------
extern "C" void kernel_launch(void* const* d_in, const int* in_sizes, int n_in,
                              void* d_out, int out_size)
{
    const float4* x    = 0;
    const float*  beta = 0;
    const void*   er   = 0;
    const void*   ec   = 0;
    for (int i = 0; i < n_in; ++i) {
        long long sz = in_sizes[i];
        if (sz == (long long)N_NODES * D_FEAT) x = (const float4*)d_in[i];
        else if (sz == 1)                      beta = (const float*)d_in[i];
        else if (sz == N_EDGES) {
            if (!er) er = d_in[i]; else ec = d_in[i];
        }
    }
    float4* out = (float4*)d_out;

    prep_kernel<<<B_NORM + B_COL + B_ROWC + B_PTR, 256>>>(x, er, ec);

    {   // phase A: warp per 32 edges
        int warps = (N_EDGES + 31) / 32;
        int blocks = (warps * 32 + 255) / 256;
        simw_kernel<<<blocks, 256>>>(x, beta);
    }
    {   // phase B: warp per row
        long long total = (long long)N_NODES * 32;
        int blocks = (int)((total + 255) / 256);
        spmm_kernel<<<blocks, 256>>>(x, out);
    }
}

// round 11
// speedup vs baseline: 1.2605x; 1.2605x over previous
#include <cuda_runtime.h>
#include <math.h>
#include <stdint.h>

#define N_NODES 100000
#define N_EDGES 1600000
#define D_FEAT  64
#define EPS     1e-7f
#define FULL    0xffffffffu

// Scratch
__device__ float g_inv[N_NODES];          // 1 / ||x_i||
__device__ int   g_col[N_EDGES];          // edge_col as int32
__device__ int   g_rowptr[N_NODES + 1];

// ---------------------------------------------------------------------------
// Packed f32x2 helpers (sm_100+; ptxas never emits these from plain C++).
// ---------------------------------------------------------------------------
__device__ __forceinline__ uint64_t ffma2(uint64_t a, uint64_t b, uint64_t c)
{
    uint64_t r;
    asm("fma.rn.f32x2 %0, %1, %2, %3;" : "=l"(r) : "l"(a), "l"(b), "l"(c));
    return r;
}
__device__ __forceinline__ uint64_t pk2(float lo, float hi)
{
    uint64_t r;
    asm("mov.b64 %0, {%1, %2};" : "=l"(r) : "f"(lo), "f"(hi));
    return r;
}
__device__ __forceinline__ void upk2(uint64_t v, float& lo, float& hi)
{
    asm("mov.b64 {%0, %1}, %2;" : "=f"(lo), "=f"(hi) : "l"(v));
}

// ---------------------------------------------------------------------------
__device__ __forceinline__ int detect_is64(const unsigned int* ec_raw)
{
    unsigned acc = 0;
    #pragma unroll
    for (int i = 1; i < 16; i += 2) acc |= ec_raw[i];
    return acc == 0u;
}

__device__ __forceinline__ int get_idx(const void* p, int e, int is64)
{
    if (is64) return (int)((const long long*)p)[e];
    return ((const int*)p)[e];
}

// ---------------------------------------------------------------------------
// Prep kernel: three jobs via block-range split (same as R6 best).
// ---------------------------------------------------------------------------
#define B_NORM 6250     // N_NODES*16 / 256
#define B_COL  6250     // N_EDGES / 256
#define B_ROW  391      // ceil((N_NODES+1)/256)

__global__ void __launch_bounds__(256)
prep_kernel(const float4* __restrict__ x4,
            const void* __restrict__ er,
            const void* __restrict__ ec)
{
    int b = blockIdx.x;
    if (b < B_NORM) {
        int t    = b * 256 + threadIdx.x;
        int node = t >> 4;
        int sub  = t & 15;
        if (node >= N_NODES) return;
        float4 a = x4[node * 16 + sub];
        float s = a.x * a.x + a.y * a.y + a.z * a.z + a.w * a.w;
        #pragma unroll
        for (int o = 8; o; o >>= 1) s += __shfl_xor_sync(FULL, s, o);
        if (sub == 0) g_inv[node] = rsqrtf(s);
    } else if (b < B_NORM + B_COL) {
        int e = (b - B_NORM) * 256 + threadIdx.x;
        if (e >= N_EDGES) return;
        int is64 = detect_is64((const unsigned int*)ec);
        g_col[e] = get_idx(ec, e, is64);
    } else {
        int i = (b - B_NORM - B_COL) * 256 + threadIdx.x;
        if (i > N_NODES) return;
        int is64 = detect_is64((const unsigned int*)ec);
        int lo = 0, hi = N_EDGES;
        while (lo < hi) {
            int mid = (lo + hi) >> 1;
            if (get_idx(er, mid, is64) < i) lo = mid + 1; else hi = mid;
        }
        g_rowptr[i] = lo;
    }
}

// ---------------------------------------------------------------------------
// Fused sim + softmax + SPMM. ONE WARP PER ROW (R6 layout), packed f32x2 math.
// Lane = (group g 0..3) x (feature f 0..7): 4 edges per iteration; each edge
// row = 8 lanes x two 16B loads (two 128B lines), viewed as 4 packed f32x2.
// w = exp(beta*(cos-1)): shift-invariant softmax, arg<=0, no running max.
// ---------------------------------------------------------------------------
__global__ void __launch_bounds__(256)
fused_row_kernel(const ulonglong2* __restrict__ x2,
                 const float* __restrict__ beta,
                 float4* __restrict__ out4)
{
    int warp = (blockIdx.x * blockDim.x + threadIdx.x) >> 5;
    if (warp >= N_NODES) return;
    int lane = threadIdx.x & 31;
    int g = lane >> 3;                    // edge slot within iteration
    int f = lane & 7;                     // feature slice

    int row = warp;
    int s = g_rowptr[row];
    int n = g_rowptr[row + 1] - s;

    ulonglong2 xr0 = x2[row * 16 + f];        // packed pairs of x[row]
    ulonglong2 xr1 = x2[row * 16 + 8 + f];
    float  bv = beta[0];
    float  bs = bv * g_inv[row];              // beta / ||x_r||

    uint64_t acc00 = 0, acc01 = 0, acc10 = 0, acc11 = 0;  // packed {0,0}
    float    wsum  = 0.f;

    const int* __restrict__ col = g_col;

    for (int base = 0; base < n; base += 32) {
        int rem = n - base;
        int cnt = rem < 32 ? rem : 32;

        // cooperative prefetch of up to 32 indices + inverse norms
        int   myc   = (lane < cnt) ? col[s + base + lane] : row;
        float myinv = g_inv[myc];
        int iters = (cnt + 3) >> 2;

        #pragma unroll 2
        for (int it = 0; it < iters; ++it) {
            int   src   = it * 4 + g;
            int   c     = __shfl_sync(FULL, myc, src);
            float invnc = __shfl_sync(FULL, myinv, src);
            bool  valid = src < cnt;

            ulonglong2 b0 = x2[c * 16 + f];
            ulonglong2 b1 = x2[c * 16 + 8 + f];

            // packed dot: 4 FFMA2 -> one f32x2 pair -> unpack-add
            uint64_t d2 = ffma2(xr0.x, b0.x, 0ull);
            d2 = ffma2(xr0.y, b0.y, d2);
            d2 = ffma2(xr1.x, b1.x, d2);
            d2 = ffma2(xr1.y, b1.y, d2);
            float dlo, dhi; upk2(d2, dlo, dhi);
            float d = dlo + dhi;
            d += __shfl_xor_sync(FULL, d, 1);
            d += __shfl_xor_sync(FULL, d, 2);
            d += __shfl_xor_sync(FULL, d, 4);

            float w = __expf(fmaf(bs * invnc, d, -bv));  // exp(beta*(cos-1))
            w = valid ? w : 0.f;
            uint64_t w2 = pk2(w, w);

            wsum += w;
            acc00 = ffma2(w2, b0.x, acc00);
            acc01 = ffma2(w2, b0.y, acc01);
            acc10 = ffma2(w2, b1.x, acc10);
            acc11 = ffma2(w2, b1.y, acc11);
        }
    }

    // unpack accumulators, then reduce the 4 edge-groups (butterfly)
    float a0, a1, a2, a3, a4, a5, a6, a7;
    upk2(acc00, a0, a1);
    upk2(acc01, a2, a3);
    upk2(acc10, a4, a5);
    upk2(acc11, a6, a7);

    #pragma unroll
    for (int o = 8; o <= 16; o <<= 1) {
        a0 += __shfl_xor_sync(FULL, a0, o);
        a1 += __shfl_xor_sync(FULL, a1, o);
        a2 += __shfl_xor_sync(FULL, a2, o);
        a3 += __shfl_xor_sync(FULL, a3, o);
        a4 += __shfl_xor_sync(FULL, a4, o);
        a5 += __shfl_xor_sync(FULL, a5, o);
        a6 += __shfl_xor_sync(FULL, a6, o);
        a7 += __shfl_xor_sync(FULL, a7, o);
        wsum += __shfl_xor_sync(FULL, wsum, o);
    }

    if (g == 0) {
        float invw = (n > 0) ? (1.f / wsum) : 0.f;
        out4[row * 16 + f]     = make_float4(a0 * invw, a1 * invw,
                                             a2 * invw, a3 * invw);
        out4[row * 16 + 8 + f] = make_float4(a4 * invw, a5 * invw,
                                             a6 * invw, a7 * invw);
    }
}

// ---------------------------------------------------------------------------
extern "C" void kernel_launch(void* const* d_in, const int* in_sizes, int n_in,
                              void* d_out, int out_size)
{
    const float4* x    = 0;
    const float*  beta = 0;
    const void*   er   = 0;
    const void*   ec   = 0;
    for (int i = 0; i < n_in; ++i) {
        long long sz = in_sizes[i];
        if (sz == (long long)N_NODES * D_FEAT) x = (const float4*)d_in[i];
        else if (sz == 1)                      beta = (const float*)d_in[i];
        else if (sz == N_EDGES) {
            if (!er) er = d_in[i]; else ec = d_in[i];
        }
    }
    float4* out = (float4*)d_out;

    prep_kernel<<<B_NORM + B_COL + B_ROW, 256>>>(x, er, ec);

    {   // one warp per row
        long long total = (long long)N_NODES * 32;
        int blocks = (int)((total + 255) / 256);
        fused_row_kernel<<<blocks, 256>>>((const ulonglong2*)x, beta, out);
    }
}